// round 2
// baseline (speedup 1.0000x reference)
#include <cuda_runtime.h>
#include <cstdint>
#include <math.h>

#define N_NODESC   50000
#define N_EDGESC   800000
#define DIM        512
#define KTOT       1024      // cat(h, agg)
#define NUM_GRAPHS 64
#define NUM_CLASSES 10

// ---------------- scratch (device globals; no allocation allowed) ----------
__device__ float g_agg[(size_t)N_NODESC * DIM];
__device__ float g_h1 [(size_t)N_NODESC * DIM];
__device__ float g_h2 [(size_t)N_NODESC * DIM];
__device__ int   g_rowptr[N_NODESC + 1];
__device__ int   g_fill  [N_NODESC];
__device__ int   g_csr   [N_EDGESC];
__device__ float g_W  [2][(size_t)2 * KTOT * DIM];   // [layer][hi rows 0..1023 | lo rows 1024..2047][512]
__device__ int   g_hcol [2][4 * DIM];
__device__ float g_hsign[2][4 * DIM];
__device__ float g_gsum[NUM_GRAPHS * DIM];
__device__ float g_gcnt[NUM_GRAPHS];
__device__ unsigned g_nz_ei;      // nonzero odd words => int32 data
__device__ unsigned g_nz_batch;

// ---------------- helpers ---------------------------------------------------
__device__ __forceinline__ float tf32rna(float x) {
    uint32_t u;
    asm("cvt.rna.tf32.f32 %0, %1;" : "=r"(u) : "f"(x));
    return __uint_as_float(u);
}
__device__ __forceinline__ float eluf(float x) { return x > 0.f ? x : expm1f(x); }

// index read that works for both int32 and (little-endian, small, non-negative) int64
__device__ __forceinline__ int idx_at(const int* p, long long i, bool is64) {
    return is64 ? p[2 * i] : p[i];
}

__device__ __forceinline__ void mma_tf32(float* d, const uint32_t* a, const uint32_t* b) {
    asm volatile(
        "mma.sync.aligned.m16n8k8.row.col.f32.tf32.tf32.f32 "
        "{%0,%1,%2,%3},{%4,%5,%6,%7},{%8,%9},{%0,%1,%2,%3};\n"
        : "+f"(d[0]), "+f"(d[1]), "+f"(d[2]), "+f"(d[3])
        : "r"(a[0]), "r"(a[1]), "r"(a[2]), "r"(a[3]), "r"(b[0]), "r"(b[1]));
}
__device__ __forceinline__ void cp16(void* dst_smem, const void* src) {
    uint32_t d = (uint32_t)__cvta_generic_to_shared(dst_smem);
    asm volatile("cp.async.cg.shared.global [%0], [%1], 16;\n" :: "r"(d), "l"(src));
}

// ---------------- dtype detection ------------------------------------------
__global__ void k_flags_init() {
    if (threadIdx.x == 0) { g_nz_ei = 0u; g_nz_batch = 0u; }
}
// OR together words at odd indices 2i+1 for i < n. Buffer is guaranteed to have
// at least 2n words in both dtype interpretations.
__global__ void k_detect(const unsigned* __restrict__ p, long long n, int which) {
    unsigned acc = 0;
    for (long long i = blockIdx.x * blockDim.x + threadIdx.x; i < n;
         i += (long long)gridDim.x * blockDim.x)
        acc |= p[2 * i + 1];
    // warp+block reduce via ballot-ish: just atomicOr per-warp leader
    acc |= __shfl_xor_sync(0xffffffffu, acc, 16);
    acc |= __shfl_xor_sync(0xffffffffu, acc, 8);
    acc |= __shfl_xor_sync(0xffffffffu, acc, 4);
    acc |= __shfl_xor_sync(0xffffffffu, acc, 2);
    acc |= __shfl_xor_sync(0xffffffffu, acc, 1);
    if ((threadIdx.x & 31) == 0 && acc) {
        if (which == 0) atomicOr(&g_nz_ei, acc);
        else            atomicOr(&g_nz_batch, acc);
    }
}

// ---------------- setup kernels --------------------------------------------
__global__ void k_zero_meta() {
    int i = blockIdx.x * blockDim.x + threadIdx.x;
    if (i <= N_NODESC) g_rowptr[i] = 0;
    if (i < NUM_GRAPHS * DIM) g_gsum[i] = 0.f;
    if (i < NUM_GRAPHS) g_gcnt[i] = 0.f;
}

__global__ void k_count(const int* __restrict__ ei) {
    bool is64 = (g_nz_ei == 0u);
    int e = blockIdx.x * blockDim.x + threadIdx.x;
    if (e < N_EDGESC) {
        int s = idx_at(ei, e, is64);
        atomicAdd(&g_rowptr[s + 1], 1);
    }
}

__global__ void k_scan() {   // single block, 1024 threads: inclusive scan of rowptr
    __shared__ int buf[1024];
    __shared__ int s_carry;
    int t = threadIdx.x;
    if (t == 0) s_carry = 0;
    __syncthreads();
    for (int base = 0; base <= N_NODESC; base += 1024) {
        int i = base + t;
        int v = (i <= N_NODESC) ? g_rowptr[i] : 0;
        buf[t] = v;
        __syncthreads();
        for (int off = 1; off < 1024; off <<= 1) {
            int add = (t >= off) ? buf[t - off] : 0;
            __syncthreads();
            buf[t] += add;
            __syncthreads();
        }
        int inc = buf[t] + s_carry;
        if (i <= N_NODESC) {
            g_rowptr[i] = inc;
            if (i < N_NODESC) g_fill[i] = inc;
        }
        __syncthreads();
        if (t == 1023) s_carry = inc;
        __syncthreads();
    }
}

__global__ void k_scatter(const int* __restrict__ ei) {
    bool is64 = (g_nz_ei == 0u);
    int e = blockIdx.x * blockDim.x + threadIdx.x;
    if (e < N_EDGESC) {
        int s = idx_at(ei, e, is64);
        int d = idx_at(ei, (long long)N_EDGESC + e, is64);
        int pos = atomicAdd(&g_fill[s], 1);
        g_csr[pos] = d;
    }
}

__global__ void k_hash(const float* __restrict__ Hm, int l) {
    int i = blockIdx.x * blockDim.x + threadIdx.x;  // i = k*512 + d
    if (i >= 4 * DIM) return;
    const float* row = Hm + (size_t)i * 128;
    int col = 0; float sgn = 0.f;
    for (int c = 0; c < 128; ++c) {
        float v = row[c];
        if (v != 0.f) { col = c; sgn = v; }
    }
    g_hcol[l][i] = col;
    g_hsign[l][i] = sgn;
}

__global__ void k_buildW(const float* __restrict__ Wp, const float* __restrict__ Ws, int l) {
    int idx = blockIdx.x * blockDim.x + threadIdx.x;
    if (idx >= KTOT * DIM) return;
    int r = idx >> 9;        // 0..1023
    int j = idx & 511;
    float w;
    if (r < 512) {
        w = Ws[r * DIM + j];
    } else {
        int d = r - 512;
        w = 0.f;
        #pragma unroll
        for (int k = 0; k < 4; ++k) {
            int c = g_hcol[l][k * DIM + d];
            w += g_hsign[l][k * DIM + d] * Wp[(size_t)(k * 128 + c) * DIM + j];
        }
    }
    float hi = tf32rna(w);
    float lo = tf32rna(w - hi);
    g_W[l][(size_t)r * DIM + j] = hi;
    g_W[l][(size_t)(r + KTOT) * DIM + j] = lo;
}

// ---------------- aggregation (gather-mean over CSR) ------------------------
__global__ void k_agg(const float* __restrict__ h, float* __restrict__ agg) {
    int n = blockIdx.x;
    int t = threadIdx.x;                 // 128 threads, float4 each => 512 cols
    int s = g_rowptr[n], e = g_rowptr[n + 1];
    float4 o;
    if (e == s) {
        o = *(const float4*)(h + (size_t)n * DIM + t * 4);
    } else {
        float4 a = make_float4(0.f, 0.f, 0.f, 0.f);
        for (int j = s; j < e; ++j) {
            int d = g_csr[j];
            float4 v = *(const float4*)(h + (size_t)d * DIM + t * 4);
            a.x += v.x; a.y += v.y; a.z += v.z; a.w += v.w;
        }
        float inv = 1.f / (float)(e - s);
        o = make_float4(a.x * inv, a.y * inv, a.z * inv, a.w * inv);
    }
    *(float4*)(agg + (size_t)n * DIM + t * 4) = o;
}

// ---------------- fused GEMM: out = elu([h|agg] @ (Whi+Wlo) + b) -------------
#define BM 128
#define BN 128
#define BK 32
#define ASTR (BK + 4)     // 36
#define BSTR (BN + 8)     // 136
#define GEMM_SMEM ((2 * BM * ASTR + 2 * 2 * BK * BSTR) * 4)

__global__ void __launch_bounds__(256, 1)
k_gemm(const float* __restrict__ Ah, const float* __restrict__ Aagg,
       const float* __restrict__ W, const float* __restrict__ bias,
       float* __restrict__ C)
{
    extern __shared__ float smem[];
    float* As = smem;                          // [2][BM][ASTR]
    float* Bs = smem + 2 * BM * ASTR;          // [2][2][BK][BSTR]  (hi/lo)

    const int tid  = threadIdx.x;
    const int lane = tid & 31;
    const int wid  = tid >> 5;
    const int g    = lane >> 2;
    const int t4   = lane & 3;
    const int wm   = (wid & 1) * 64;
    const int wn   = (wid >> 1) * 32;
    const int m0   = blockIdx.y * BM;
    const int n0   = blockIdx.x * BN;

    const int ar   = tid >> 3;          // 0..31
    const int ac   = (tid & 7) << 2;    // 0..28
    const int brow = tid >> 5;          // 0..7
    const int bcol = (tid & 31) << 2;   // 0..124

    float acc[4][4][4];
    #pragma unroll
    for (int i = 0; i < 4; ++i)
        #pragma unroll
        for (int j = 0; j < 4; ++j)
            #pragma unroll
            for (int k = 0; k < 4; ++k) acc[i][j][k] = 0.f;

    float4 areg[4];

    auto loadA = [&](int kt) {
        const int kk = kt * BK;
        const float* Ab = (kk & 512) ? Aagg : Ah;
        const int kc = (kk & 511) + ac;
        #pragma unroll
        for (int p = 0; p < 4; ++p) {
            int row = m0 + ar + 32 * p;
            if (row < N_NODESC) areg[p] = *(const float4*)(Ab + (size_t)row * DIM + kc);
            else                areg[p] = make_float4(0.f, 0.f, 0.f, 0.f);
        }
    };
    auto storeA = [&](int st) {
        float* base = As + st * BM * ASTR;
        #pragma unroll
        for (int p = 0; p < 4; ++p) {
            float4 v = areg[p];
            v.x = tf32rna(v.x); v.y = tf32rna(v.y);
            v.z = tf32rna(v.z); v.w = tf32rna(v.w);
            *(float4*)(base + (ar + 32 * p) * ASTR + ac) = v;
        }
    };
    auto loadB = [&](int kt, int st) {
        const int kk = kt * BK;
        float* base = Bs + st * (2 * BK * BSTR);
        #pragma unroll
        for (int hf = 0; hf < 2; ++hf)
            #pragma unroll
            for (int p = 0; p < 4; ++p) {
                int r = brow + 8 * p;
                cp16(base + hf * BK * BSTR + r * BSTR + bcol,
                     W + (size_t)(kk + hf * KTOT + r) * DIM + n0 + bcol);
            }
    };

    loadA(0); storeA(0);
    loadB(0, 0);
    asm volatile("cp.async.commit_group;\n");
    asm volatile("cp.async.wait_group 0;\n");
    __syncthreads();

    const int KT = KTOT / BK;   // 32
    for (int kt = 0; kt < KT; ++kt) {
        int cur = kt & 1, nxt = cur ^ 1;
        if (kt + 1 < KT) {
            loadA(kt + 1);
            loadB(kt + 1, nxt);
            asm volatile("cp.async.commit_group;\n");
        }
        const float* Asb = As + cur * BM * ASTR;
        const float* Bsb = Bs + cur * (2 * BK * BSTR);
        #pragma unroll
        for (int ks = 0; ks < 4; ++ks) {
            uint32_t af[4][4];
            #pragma unroll
            for (int mi = 0; mi < 4; ++mi) {
                const float* ap = Asb + (wm + mi * 16 + g) * ASTR + ks * 8 + t4;
                af[mi][0] = __float_as_uint(ap[0]);
                af[mi][1] = __float_as_uint(ap[8 * ASTR]);
                af[mi][2] = __float_as_uint(ap[4]);
                af[mi][3] = __float_as_uint(ap[8 * ASTR + 4]);
            }
            #pragma unroll
            for (int hf = 0; hf < 2; ++hf) {
                const float* bb = Bsb + hf * BK * BSTR;
                uint32_t bf[4][2];
                #pragma unroll
                for (int ni = 0; ni < 4; ++ni) {
                    const float* bp = bb + (ks * 8 + t4) * BSTR + wn + ni * 8 + g;
                    bf[ni][0] = __float_as_uint(bp[0]);
                    bf[ni][1] = __float_as_uint(bp[4 * BSTR]);
                }
                #pragma unroll
                for (int mi = 0; mi < 4; ++mi)
                    #pragma unroll
                    for (int ni = 0; ni < 4; ++ni)
                        mma_tf32(acc[mi][ni], af[mi], bf[ni]);
            }
        }
        if (kt + 1 < KT) {
            storeA(nxt);
            asm volatile("cp.async.wait_group 0;\n");
        }
        __syncthreads();
    }

    // epilogue: bias + elu
    #pragma unroll
    for (int mi = 0; mi < 4; ++mi) {
        int r0 = m0 + wm + mi * 16 + g;
        #pragma unroll
        for (int ni = 0; ni < 4; ++ni) {
            int col = n0 + wn + ni * 8 + 2 * t4;
            float bb0 = bias[col], bb1 = bias[col + 1];
            if (r0 < N_NODESC) {
                float2 v;
                v.x = eluf(acc[mi][ni][0] + bb0);
                v.y = eluf(acc[mi][ni][1] + bb1);
                *(float2*)(C + (size_t)r0 * DIM + col) = v;
            }
            if (r0 + 8 < N_NODESC) {
                float2 v;
                v.x = eluf(acc[mi][ni][2] + bb0);
                v.y = eluf(acc[mi][ni][3] + bb1);
                *(float2*)(C + (size_t)(r0 + 8) * DIM + col) = v;
            }
        }
    }
}

// ---------------- pooling + classifier --------------------------------------
__global__ void k_pool(const float* __restrict__ h, const int* __restrict__ batch) {
    bool is64 = (g_nz_batch == 0u);
    int d  = blockIdx.y * 128 + threadIdx.x;
    int n0 = blockIdx.x * 128;
    int ne = min(n0 + 128, N_NODESC);
    int cur = idx_at(batch, n0, is64);
    float acc = 0.f;
    for (int n = n0; n < ne; ++n) {
        int b = idx_at(batch, n, is64);
        if (b != cur) { atomicAdd(&g_gsum[cur * DIM + d], acc); acc = 0.f; cur = b; }
        acc += h[(size_t)n * DIM + d];
    }
    atomicAdd(&g_gsum[cur * DIM + d], acc);
}

__global__ void k_cnt(const int* __restrict__ batch) {
    bool is64 = (g_nz_batch == 0u);
    int n = blockIdx.x * blockDim.x + threadIdx.x;
    if (n < N_NODESC) atomicAdd(&g_gcnt[idx_at(batch, n, is64)], 1.f);
}

__global__ void k_cls(const float* __restrict__ Wc, const float* __restrict__ bc,
                      float* __restrict__ out) {
    int gid = blockIdx.x;
    int t = threadIdx.x;               // 128
    __shared__ float gv[DIM];
    __shared__ float red[NUM_CLASSES][128];
    float inv = 1.f / fmaxf(g_gcnt[gid], 1.f);
    for (int d = t; d < DIM; d += 128) gv[d] = g_gsum[gid * DIM + d] * inv;
    __syncthreads();
    float p[NUM_CLASSES];
    #pragma unroll
    for (int c = 0; c < NUM_CLASSES; ++c) p[c] = 0.f;
    for (int d = t; d < DIM; d += 128) {
        float v = gv[d];
        #pragma unroll
        for (int c = 0; c < NUM_CLASSES; ++c) p[c] += v * Wc[d * NUM_CLASSES + c];
    }
    #pragma unroll
    for (int c = 0; c < NUM_CLASSES; ++c) red[c][t] = p[c];
    __syncthreads();
    for (int off = 64; off > 0; off >>= 1) {
        if (t < off)
            #pragma unroll
            for (int c = 0; c < NUM_CLASSES; ++c) red[c][t] += red[c][t + off];
        __syncthreads();
    }
    if (t < NUM_CLASSES) out[gid * NUM_CLASSES + t] = red[t][0] + bc[t];
}

// ---------------- launch -----------------------------------------------------
extern "C" void kernel_launch(void* const* d_in, const int* in_sizes, int n_in,
                              void* d_out, int out_size) {
    const float* x     = (const float*)d_in[0];
    const int*   ei    = (const int*)d_in[1];     // int32 or int64 — detected on device
    const int*   batch = (const int*)d_in[2];
    const float* Hm1   = (const float*)d_in[3];
    const float* Wp1   = (const float*)d_in[4];
    const float* Ws1   = (const float*)d_in[5];
    const float* b1    = (const float*)d_in[6];
    const float* Hm2   = (const float*)d_in[7];
    const float* Wp2   = (const float*)d_in[8];
    const float* Ws2   = (const float*)d_in[9];
    const float* b2    = (const float*)d_in[10];
    const float* Wc    = (const float*)d_in[11];
    const float* bc    = (const float*)d_in[12];
    float*       out   = (float*)d_out;

    float *aggp, *h1p, *h2p, *wp;
    cudaGetSymbolAddress((void**)&aggp, g_agg);
    cudaGetSymbolAddress((void**)&h1p,  g_h1);
    cudaGetSymbolAddress((void**)&h2p,  g_h2);
    cudaGetSymbolAddress((void**)&wp,   g_W);
    float* W0 = wp;
    float* W1 = wp + (size_t)2 * KTOT * DIM;

    cudaFuncSetAttribute(k_gemm, cudaFuncAttributeMaxDynamicSharedMemorySize, GEMM_SMEM);

    // dtype detection (reads only within the smaller (int32) interpretation)
    k_flags_init<<<1, 32>>>();
    k_detect<<<256, 256>>>((const unsigned*)ei, N_EDGESC, 0);       // words [1 .. 1.6M-1]
    k_detect<<<64, 256>>>((const unsigned*)batch, N_NODESC / 2, 1); // words [1 .. 49999]

    // setup
    k_zero_meta<<<196, 256>>>();
    k_count<<<(N_EDGESC + 255) / 256, 256>>>(ei);
    k_scan<<<1, 1024>>>();
    k_scatter<<<(N_EDGESC + 255) / 256, 256>>>(ei);
    k_hash<<<8, 256>>>(Hm1, 0);
    k_hash<<<8, 256>>>(Hm2, 1);
    k_buildW<<<(KTOT * DIM + 255) / 256, 256>>>(Wp1, Ws1, 0);
    k_buildW<<<(KTOT * DIM + 255) / 256, 256>>>(Wp2, Ws2, 1);

    dim3 ggrid(DIM / BN, (N_NODESC + BM - 1) / BM);

    // layer 1
    k_agg<<<N_NODESC, 128>>>(x, aggp);
    k_gemm<<<ggrid, 256, GEMM_SMEM>>>(x, aggp, W0, b1, h1p);

    // layer 2
    k_agg<<<N_NODESC, 128>>>(h1p, aggp);
    k_gemm<<<ggrid, 256, GEMM_SMEM>>>(h1p, aggp, W1, b2, h2p);

    // pool + classify
    k_pool<<<dim3((N_NODESC + 127) / 128, 4), 128>>>(h2p, batch);
    k_cnt<<<196, 256>>>(batch);
    k_cls<<<NUM_GRAPHS, 128>>>(Wc, bc, out);
}

// round 3
// speedup vs baseline: 1.6741x; 1.6741x over previous
#include <cuda_runtime.h>
#include <cstdint>
#include <math.h>

#define N_NODESC   50000
#define N_EDGESC   800000
#define DIM        512
#define KTOT       1024      // cat(h, agg)
#define NUM_GRAPHS 64
#define NUM_CLASSES 10
#define SCAN_NB    ((N_NODESC + 1 + 1023) / 1024)   // 49

// ---------------- scratch (device globals; no allocation allowed) ----------
__device__ float g_agg[(size_t)N_NODESC * DIM];
__device__ float g_h1 [(size_t)N_NODESC * DIM];
__device__ float g_h2 [(size_t)N_NODESC * DIM];
__device__ int   g_rowptr[N_NODESC + 1];
__device__ int   g_fill  [N_NODESC];
__device__ int   g_csr   [N_EDGESC];
__device__ float g_W  [2][(size_t)KTOT * DIM];   // [layer][1024][512], tf32-rounded
__device__ int   g_hcol [2][4 * DIM];
__device__ float g_hsign[2][4 * DIM];
__device__ float g_gsum[NUM_GRAPHS * DIM];
__device__ float g_gcnt[NUM_GRAPHS];
__device__ int   g_bsum[64];                     // scan block partials (inclusive)
__device__ unsigned g_nz_ei;      // nonzero odd words => int32 data
__device__ unsigned g_nz_batch;

// ---------------- helpers ---------------------------------------------------
__device__ __forceinline__ float tf32rna(float x) {
    uint32_t u;
    asm("cvt.rna.tf32.f32 %0, %1;" : "=r"(u) : "f"(x));
    return __uint_as_float(u);
}
__device__ __forceinline__ float eluf(float x) { return x > 0.f ? x : expm1f(x); }

// index read that works for both int32 and (little-endian, small, non-negative) int64
__device__ __forceinline__ int idx_at(const int* p, long long i, bool is64) {
    return is64 ? p[2 * i] : p[i];
}

__device__ __forceinline__ void mma_tf32(float* d, const uint32_t* a, const uint32_t* b) {
    asm volatile(
        "mma.sync.aligned.m16n8k8.row.col.f32.tf32.tf32.f32 "
        "{%0,%1,%2,%3},{%4,%5,%6,%7},{%8,%9},{%0,%1,%2,%3};\n"
        : "+f"(d[0]), "+f"(d[1]), "+f"(d[2]), "+f"(d[3])
        : "r"(a[0]), "r"(a[1]), "r"(a[2]), "r"(a[3]), "r"(b[0]), "r"(b[1]));
}
__device__ __forceinline__ void cp16(void* dst_smem, const void* src) {
    uint32_t d = (uint32_t)__cvta_generic_to_shared(dst_smem);
    asm volatile("cp.async.cg.shared.global [%0], [%1], 16;\n" :: "r"(d), "l"(src));
}

// ---------------- dtype detection ------------------------------------------
__global__ void k_flags_init() {
    if (threadIdx.x == 0) { g_nz_ei = 0u; g_nz_batch = 0u; }
}
__global__ void k_detect(const unsigned* __restrict__ p, long long n, int which) {
    unsigned acc = 0;
    for (long long i = blockIdx.x * blockDim.x + threadIdx.x; i < n;
         i += (long long)gridDim.x * blockDim.x)
        acc |= p[2 * i + 1];
    acc |= __shfl_xor_sync(0xffffffffu, acc, 16);
    acc |= __shfl_xor_sync(0xffffffffu, acc, 8);
    acc |= __shfl_xor_sync(0xffffffffu, acc, 4);
    acc |= __shfl_xor_sync(0xffffffffu, acc, 2);
    acc |= __shfl_xor_sync(0xffffffffu, acc, 1);
    if ((threadIdx.x & 31) == 0 && acc) {
        if (which == 0) atomicOr(&g_nz_ei, acc);
        else            atomicOr(&g_nz_batch, acc);
    }
}

// ---------------- setup kernels --------------------------------------------
__global__ void k_zero_meta() {
    int i = blockIdx.x * blockDim.x + threadIdx.x;
    if (i <= N_NODESC) g_rowptr[i] = 0;
    if (i < NUM_GRAPHS * DIM) g_gsum[i] = 0.f;
    if (i < NUM_GRAPHS) g_gcnt[i] = 0.f;
}

__global__ void k_count(const int* __restrict__ ei) {
    bool is64 = (g_nz_ei == 0u);
    int e = blockIdx.x * blockDim.x + threadIdx.x;
    if (e < N_EDGESC) {
        int s = idx_at(ei, e, is64);
        atomicAdd(&g_rowptr[s + 1], 1);
    }
}

// 3-phase parallel scan of g_rowptr[0..N_NODESC] (inclusive)
__global__ void k_scan1() {
    __shared__ int wsum[8];
    int b = blockIdx.x, t = threadIdx.x;
    int base = b * 1024 + t * 4;
    int v0, v1, v2, v3;
    v0 = (base + 0 <= N_NODESC) ? g_rowptr[base + 0] : 0;
    v1 = (base + 1 <= N_NODESC) ? g_rowptr[base + 1] : 0;
    v2 = (base + 2 <= N_NODESC) ? g_rowptr[base + 2] : 0;
    v3 = (base + 3 <= N_NODESC) ? g_rowptr[base + 3] : 0;
    v1 += v0; v2 += v1; v3 += v2;           // thread-local inclusive
    int lane = t & 31, w = t >> 5;
    int s = v3;
    #pragma unroll
    for (int o = 1; o < 32; o <<= 1) {
        int n = __shfl_up_sync(0xffffffffu, s, o);
        if (lane >= o) s += n;
    }
    if (lane == 31) wsum[w] = s;
    __syncthreads();
    if (t < 8) {
        int x = wsum[t];
        #pragma unroll
        for (int o = 1; o < 8; o <<= 1) {
            int n = __shfl_up_sync(0x000000ffu, x, o);
            if (t >= o) x += n;
        }
        wsum[t] = x;
    }
    __syncthreads();
    int excl = (w ? wsum[w - 1] : 0) + (s - v3);   // exclusive prefix of this thread
    v0 += excl; v1 += excl; v2 += excl; v3 += excl;
    if (base + 0 <= N_NODESC) g_rowptr[base + 0] = v0;
    if (base + 1 <= N_NODESC) g_rowptr[base + 1] = v1;
    if (base + 2 <= N_NODESC) g_rowptr[base + 2] = v2;
    if (base + 3 <= N_NODESC) g_rowptr[base + 3] = v3;
    if (t == 0) g_bsum[b] = wsum[7];
}

__global__ void k_scan2() {   // 1 block, 64 threads: inclusive scan of block sums
    __shared__ int sh[64];
    int t = threadIdx.x;
    sh[t] = (t < SCAN_NB) ? g_bsum[t] : 0;
    __syncthreads();
    for (int o = 1; o < 64; o <<= 1) {
        int a = (t >= o) ? sh[t - o] : 0;
        __syncthreads();
        sh[t] += a;
        __syncthreads();
    }
    g_bsum[t] = sh[t];
}

__global__ void k_scan3() {
    int b = blockIdx.x, t = threadIdx.x;
    int add = b ? g_bsum[b - 1] : 0;
    int base = b * 1024 + t * 4;
    #pragma unroll
    for (int i = 0; i < 4; ++i) {
        int idx = base + i;
        if (idx <= N_NODESC) {
            int r = g_rowptr[idx] + add;
            g_rowptr[idx] = r;
            if (idx < N_NODESC) g_fill[idx] = r;
        }
    }
}

__global__ void k_scatter(const int* __restrict__ ei) {
    bool is64 = (g_nz_ei == 0u);
    int e = blockIdx.x * blockDim.x + threadIdx.x;
    if (e < N_EDGESC) {
        int s = idx_at(ei, e, is64);
        int d = idx_at(ei, (long long)N_EDGESC + e, is64);
        int pos = atomicAdd(&g_fill[s], 1);
        g_csr[pos] = d;
    }
}

__global__ void k_hash(const float* __restrict__ Hm, int l) {
    int i = blockIdx.x * blockDim.x + threadIdx.x;  // i = k*512 + d
    if (i >= 4 * DIM) return;
    const float* row = Hm + (size_t)i * 128;
    int col = 0; float sgn = 0.f;
    for (int c = 0; c < 128; ++c) {
        float v = row[c];
        if (v != 0.f) { col = c; sgn = v; }
    }
    g_hcol[l][i] = col;
    g_hsign[l][i] = sgn;
}

__global__ void k_buildW(const float* __restrict__ Wp, const float* __restrict__ Ws, int l) {
    int idx = blockIdx.x * blockDim.x + threadIdx.x;
    if (idx >= KTOT * DIM) return;
    int r = idx >> 9;        // 0..1023
    int j = idx & 511;
    float w;
    if (r < 512) {
        w = Ws[r * DIM + j];
    } else {
        int d = r - 512;
        w = 0.f;
        #pragma unroll
        for (int k = 0; k < 4; ++k) {
            int c = g_hcol[l][k * DIM + d];
            w += g_hsign[l][k * DIM + d] * Wp[(size_t)(k * 128 + c) * DIM + j];
        }
    }
    g_W[l][(size_t)r * DIM + j] = tf32rna(w);
}

// ---------------- aggregation (gather-mean over CSR) ------------------------
__global__ void k_agg(const float* __restrict__ h, float* __restrict__ agg) {
    int n = blockIdx.x;
    int t = threadIdx.x;                 // 128 threads, float4 each => 512 cols
    int s = g_rowptr[n], e = g_rowptr[n + 1];
    float4 o;
    if (e == s) {
        o = *(const float4*)(h + (size_t)n * DIM + t * 4);
    } else {
        float4 a = make_float4(0.f, 0.f, 0.f, 0.f);
        for (int j = s; j < e; ++j) {
            int d = g_csr[j];
            float4 v = *(const float4*)(h + (size_t)d * DIM + t * 4);
            a.x += v.x; a.y += v.y; a.z += v.z; a.w += v.w;
        }
        float inv = 1.f / (float)(e - s);
        o = make_float4(a.x * inv, a.y * inv, a.z * inv, a.w * inv);
    }
    *(float4*)(agg + (size_t)n * DIM + t * 4) = o;
}

// ---------------- fused GEMM: out = elu([h|agg] @ W + b) ---------------------
#define BM 128
#define BN 128
#define BK 32
#define ASTR (BK + 4)     // 36
#define BSTR (BN + 8)     // 136
#define GEMM_SMEM ((2 * BM * ASTR + 2 * BK * BSTR) * 4)   // 71680 B -> 2 CTA/SM

__global__ void __launch_bounds__(256, 2)
k_gemm(const float* __restrict__ Ah, const float* __restrict__ Aagg,
       const float* __restrict__ W, const float* __restrict__ bias,
       float* __restrict__ C)
{
    extern __shared__ float smem[];
    float* As = smem;                          // [2][BM][ASTR]
    float* Bs = smem + 2 * BM * ASTR;          // [2][BK][BSTR]

    const int tid  = threadIdx.x;
    const int lane = tid & 31;
    const int wid  = tid >> 5;
    const int g    = lane >> 2;
    const int t4   = lane & 3;
    const int wm   = (wid & 1) * 64;
    const int wn   = (wid >> 1) * 32;
    const int m0   = blockIdx.y * BM;
    const int n0   = blockIdx.x * BN;

    const int ar   = tid >> 3;          // 0..31
    const int ac   = (tid & 7) << 2;    // 0..28
    const int brow = tid >> 5;          // 0..7
    const int bcol = (tid & 31) << 2;   // 0..124

    float acc[4][4][4];
    #pragma unroll
    for (int i = 0; i < 4; ++i)
        #pragma unroll
        for (int j = 0; j < 4; ++j)
            #pragma unroll
            for (int k = 0; k < 4; ++k) acc[i][j][k] = 0.f;

    float4 areg[4];

    auto loadA = [&](int kt) {
        const int kk = kt * BK;
        const float* Ab = (kk & 512) ? Aagg : Ah;
        const int kc = (kk & 511) + ac;
        #pragma unroll
        for (int p = 0; p < 4; ++p) {
            int row = m0 + ar + 32 * p;
            if (row < N_NODESC) areg[p] = *(const float4*)(Ab + (size_t)row * DIM + kc);
            else                areg[p] = make_float4(0.f, 0.f, 0.f, 0.f);
        }
    };
    auto storeA = [&](int st) {
        float* base = As + st * BM * ASTR;
        #pragma unroll
        for (int p = 0; p < 4; ++p) {
            float4 v = areg[p];
            v.x = tf32rna(v.x); v.y = tf32rna(v.y);
            v.z = tf32rna(v.z); v.w = tf32rna(v.w);
            *(float4*)(base + (ar + 32 * p) * ASTR + ac) = v;
        }
    };
    auto loadB = [&](int kt, int st) {
        const int kk = kt * BK;
        float* base = Bs + st * (BK * BSTR);
        #pragma unroll
        for (int p = 0; p < 4; ++p) {
            int r = brow + 8 * p;
            cp16(base + r * BSTR + bcol,
                 W + (size_t)(kk + r) * DIM + n0 + bcol);
        }
    };

    loadA(0); storeA(0);
    loadB(0, 0);
    asm volatile("cp.async.commit_group;\n");
    asm volatile("cp.async.wait_group 0;\n");
    __syncthreads();

    const int KT = KTOT / BK;   // 32
    for (int kt = 0; kt < KT; ++kt) {
        int cur = kt & 1, nxt = cur ^ 1;
        if (kt + 1 < KT) {
            loadA(kt + 1);
            loadB(kt + 1, nxt);
            asm volatile("cp.async.commit_group;\n");
        }
        const float* Asb = As + cur * BM * ASTR;
        const float* Bsb = Bs + cur * (BK * BSTR);
        #pragma unroll
        for (int ks = 0; ks < 4; ++ks) {
            uint32_t af[4][4];
            #pragma unroll
            for (int mi = 0; mi < 4; ++mi) {
                const float* ap = Asb + (wm + mi * 16 + g) * ASTR + ks * 8 + t4;
                af[mi][0] = __float_as_uint(ap[0]);
                af[mi][1] = __float_as_uint(ap[8 * ASTR]);
                af[mi][2] = __float_as_uint(ap[4]);
                af[mi][3] = __float_as_uint(ap[8 * ASTR + 4]);
            }
            uint32_t bf[4][2];
            #pragma unroll
            for (int ni = 0; ni < 4; ++ni) {
                const float* bp = Bsb + (ks * 8 + t4) * BSTR + wn + ni * 8 + g;
                bf[ni][0] = __float_as_uint(bp[0]);
                bf[ni][1] = __float_as_uint(bp[4 * BSTR]);
            }
            #pragma unroll
            for (int mi = 0; mi < 4; ++mi)
                #pragma unroll
                for (int ni = 0; ni < 4; ++ni)
                    mma_tf32(acc[mi][ni], af[mi], bf[ni]);
        }
        if (kt + 1 < KT) {
            storeA(nxt);
            asm volatile("cp.async.wait_group 0;\n");
        }
        __syncthreads();
    }

    // epilogue: bias + elu
    #pragma unroll
    for (int mi = 0; mi < 4; ++mi) {
        int r0 = m0 + wm + mi * 16 + g;
        #pragma unroll
        for (int ni = 0; ni < 4; ++ni) {
            int col = n0 + wn + ni * 8 + 2 * t4;
            float bb0 = bias[col], bb1 = bias[col + 1];
            if (r0 < N_NODESC) {
                float2 v;
                v.x = eluf(acc[mi][ni][0] + bb0);
                v.y = eluf(acc[mi][ni][1] + bb1);
                *(float2*)(C + (size_t)r0 * DIM + col) = v;
            }
            if (r0 + 8 < N_NODESC) {
                float2 v;
                v.x = eluf(acc[mi][ni][2] + bb0);
                v.y = eluf(acc[mi][ni][3] + bb1);
                *(float2*)(C + (size_t)(r0 + 8) * DIM + col) = v;
            }
        }
    }
}

// ---------------- pooling + classifier --------------------------------------
__global__ void k_pool(const float* __restrict__ h, const int* __restrict__ batch) {
    bool is64 = (g_nz_batch == 0u);
    int d  = blockIdx.y * 128 + threadIdx.x;
    int n0 = blockIdx.x * 128;
    int ne = min(n0 + 128, N_NODESC);
    int cur = idx_at(batch, n0, is64);
    float acc = 0.f;
    for (int n = n0; n < ne; ++n) {
        int b = idx_at(batch, n, is64);
        if (b != cur) { atomicAdd(&g_gsum[cur * DIM + d], acc); acc = 0.f; cur = b; }
        acc += h[(size_t)n * DIM + d];
    }
    atomicAdd(&g_gsum[cur * DIM + d], acc);
}

__global__ void k_cnt(const int* __restrict__ batch) {
    bool is64 = (g_nz_batch == 0u);
    int n = blockIdx.x * blockDim.x + threadIdx.x;
    if (n < N_NODESC) atomicAdd(&g_gcnt[idx_at(batch, n, is64)], 1.f);
}

__global__ void k_cls(const float* __restrict__ Wc, const float* __restrict__ bc,
                      float* __restrict__ out) {
    int gid = blockIdx.x;
    int t = threadIdx.x;               // 128
    __shared__ float gv[DIM];
    __shared__ float red[NUM_CLASSES][128];
    float inv = 1.f / fmaxf(g_gcnt[gid], 1.f);
    for (int d = t; d < DIM; d += 128) gv[d] = g_gsum[gid * DIM + d] * inv;
    __syncthreads();
    float p[NUM_CLASSES];
    #pragma unroll
    for (int c = 0; c < NUM_CLASSES; ++c) p[c] = 0.f;
    for (int d = t; d < DIM; d += 128) {
        float v = gv[d];
        #pragma unroll
        for (int c = 0; c < NUM_CLASSES; ++c) p[c] += v * Wc[d * NUM_CLASSES + c];
    }
    #pragma unroll
    for (int c = 0; c < NUM_CLASSES; ++c) red[c][t] = p[c];
    __syncthreads();
    for (int off = 64; off > 0; off >>= 1) {
        if (t < off)
            #pragma unroll
            for (int c = 0; c < NUM_CLASSES; ++c) red[c][t] += red[c][t + off];
        __syncthreads();
    }
    if (t < NUM_CLASSES) out[gid * NUM_CLASSES + t] = red[t][0] + bc[t];
}

// ---------------- launch -----------------------------------------------------
extern "C" void kernel_launch(void* const* d_in, const int* in_sizes, int n_in,
                              void* d_out, int out_size) {
    const float* x     = (const float*)d_in[0];
    const int*   ei    = (const int*)d_in[1];     // int32 or int64 — detected on device
    const int*   batch = (const int*)d_in[2];
    const float* Hm1   = (const float*)d_in[3];
    const float* Wp1   = (const float*)d_in[4];
    const float* Ws1   = (const float*)d_in[5];
    const float* b1    = (const float*)d_in[6];
    const float* Hm2   = (const float*)d_in[7];
    const float* Wp2   = (const float*)d_in[8];
    const float* Ws2   = (const float*)d_in[9];
    const float* b2    = (const float*)d_in[10];
    const float* Wc    = (const float*)d_in[11];
    const float* bc    = (const float*)d_in[12];
    float*       out   = (float*)d_out;

    float *aggp, *h1p, *h2p, *wp;
    cudaGetSymbolAddress((void**)&aggp, g_agg);
    cudaGetSymbolAddress((void**)&h1p,  g_h1);
    cudaGetSymbolAddress((void**)&h2p,  g_h2);
    cudaGetSymbolAddress((void**)&wp,   g_W);
    float* W0 = wp;
    float* W1 = wp + (size_t)KTOT * DIM;

    cudaFuncSetAttribute(k_gemm, cudaFuncAttributeMaxDynamicSharedMemorySize, GEMM_SMEM);

    // dtype detection (reads only within the smaller (int32) interpretation)
    k_flags_init<<<1, 32>>>();
    k_detect<<<256, 256>>>((const unsigned*)ei, N_EDGESC, 0);
    k_detect<<<64, 256>>>((const unsigned*)batch, N_NODESC / 2, 1);

    // setup
    k_zero_meta<<<196, 256>>>();
    k_count<<<(N_EDGESC + 255) / 256, 256>>>(ei);
    k_scan1<<<SCAN_NB, 256>>>();
    k_scan2<<<1, 64>>>();
    k_scan3<<<SCAN_NB, 256>>>();
    k_scatter<<<(N_EDGESC + 255) / 256, 256>>>(ei);
    k_hash<<<8, 256>>>(Hm1, 0);
    k_hash<<<8, 256>>>(Hm2, 1);
    k_buildW<<<(KTOT * DIM + 255) / 256, 256>>>(Wp1, Ws1, 0);
    k_buildW<<<(KTOT * DIM + 255) / 256, 256>>>(Wp2, Ws2, 1);

    dim3 ggrid(DIM / BN, (N_NODESC + BM - 1) / BM);

    // layer 1
    k_agg<<<N_NODESC, 128>>>(x, aggp);
    k_gemm<<<ggrid, 256, GEMM_SMEM>>>(x, aggp, W0, b1, h1p);

    // layer 2
    k_agg<<<N_NODESC, 128>>>(h1p, aggp);
    k_gemm<<<ggrid, 256, GEMM_SMEM>>>(h1p, aggp, W1, b2, h2p);

    // pool + classify
    k_pool<<<dim3((N_NODESC + 127) / 128, 4), 128>>>(h2p, batch);
    k_cnt<<<196, 256>>>(batch);
    k_cls<<<NUM_GRAPHS, 128>>>(Wc, bc, out);
}